// round 16
// baseline (speedup 1.0000x reference)
#include <cuda_runtime.h>
#include <cuda_bf16.h>

#define MEM   1000
#define NSLOT 1024          /* padded slot count (rows 1000..1023 zero) */
#define KEY   64
#define VAL   128
#define DIN   512
#define BSS   512
#define BQ    65536

typedef unsigned long long u64;
typedef unsigned int u32;

// ---------------- packed f32x2 helpers (Blackwell sm_103a) ----------------
#define PACKF_F32X2(out, a, b) \
    asm("mov.b64 %0, {%1, %2};" : "=l"(out) : "f"(a), "f"(b))
#define UNPACKF_F32X2(a, b, in) \
    asm("mov.b64 {%0, %1}, %2;" : "=f"(a), "=f"(b) : "l"(in))
#define FMA_F32X2(d, a, b, c) \
    asm("fma.rn.f32x2 %0, %1, %2, %3;" : "=l"(d) : "l"(a), "l"(b), "l"(c))

// ---------------- bf16 HMMA m16n8k16 ----------------
#define MMA_BF16(d, a, b0, b1) \
    asm volatile("mma.sync.aligned.m16n8k16.row.col.f32.bf16.bf16.f32 " \
        "{%0,%1,%2,%3}, {%4,%5,%6,%7}, {%8,%9}, {%0,%1,%2,%3};" \
        : "+f"((d)[0]), "+f"((d)[1]), "+f"((d)[2]), "+f"((d)[3]) \
        : "r"((a)[0]), "r"((a)[1]), "r"((a)[2]), "r"((a)[3]), "r"(b0), "r"(b1))

// split x,y into hi/lo bf16 pairs (packed b32; low half = first element)
__device__ __forceinline__ void split2(float x, float y, u32& hi, u32& lo) {
    __nv_bfloat16 hx = __float2bfloat16_rn(x), hy = __float2bfloat16_rn(y);
    __nv_bfloat16 lx = __float2bfloat16_rn(x - __bfloat162float(hx));
    __nv_bfloat16 ly = __float2bfloat16_rn(y - __bfloat162float(hy));
    __nv_bfloat162 H = __halves2bfloat162(hx, hy);
    __nv_bfloat162 L = __halves2bfloat162(lx, ly);
    hi = *reinterpret_cast<u32*>(&H);
    lo = *reinterpret_cast<u32*>(&L);
}

// cp.async 16B copy
__device__ __forceinline__ void cp16(u32 dst_smem, const void* src) {
    asm volatile("cp.async.ca.shared.global [%0], [%1], 16;" :: "r"(dst_smem), "l"(src));
}
#define CP_COMMIT() asm volatile("cp.async.commit_group;")
#define CP_WAIT(n)  asm volatile("cp.async.wait_group %0;" :: "n"(n))

// ---------------- device scratch (no allocations allowed) ----------------
__device__ __align__(16) float g_bWkp[DIN * KEY];
__device__ __align__(16) float g_bias2[KEY];
__device__ __align__(16) float g_proj_keys[BSS * KEY];
__device__ __align__(16) float g_proj_vals[BSS * VAL];
__device__             int   g_rank[MEM];
// pre-split bf16 hi/lo planes (built once in k_scatter)
__device__ __align__(16) u32 g_khi[NSLOT * 32];            // [slot][key-pair]
__device__ __align__(16) u32 g_klo[NSLOT * 32];
__device__ __align__(16) u32 g_vhi[16 * 128 * 32];         // [chunk][col][slot-pair]
__device__ __align__(16) u32 g_vlo[16 * 128 * 32];
__device__ __align__(16) float g_query_feat[BQ * KEY];
__device__ __align__(16) float g_proj_q[BQ * KEY];
__device__ __align__(16) float g_retr_fb[BQ * VAL];
__device__ __align__(16) float g_pred_fb[BQ];
__device__             float g_loss_part[BQ / 64];

// ---------------- fuse: bWkp = bW @ kpW ; bias2 = bb @ kpW + kpb ----------------
__global__ void k_fuse(const float* __restrict__ bW, const float* __restrict__ bb,
                       const float* __restrict__ kpW, const float* __restrict__ kpb) {
    __shared__ float kp_s[KEY * KEY];
    int tid = threadIdx.x;
    for (int i = tid; i < KEY * KEY / 4; i += 256)
        ((float4*)kp_s)[i] = ((const float4*)kpW)[i];
    __syncthreads();
    int d0 = blockIdx.x * 64;
    for (int o = tid; o < 64 * 64; o += 256) {
        int dr = o >> 6, c = o & 63;
        const float* brow = bW + (size_t)(d0 + dr) * KEY;
        float a = 0.f;
        for (int k = 0; k < KEY; k++) a += brow[k] * kp_s[k * 64 + c];
        g_bWkp[(d0 + dr) * KEY + c] = a;
    }
    if (blockIdx.x == 0 && tid < KEY) {
        float a = kpb[tid];
        for (int k = 0; k < KEY; k++) a += bb[k] * kp_s[k * 64 + tid];
        g_bias2[tid] = a;
    }
}

// ---------------- prep: proj_keys (fused weights), proj_vals, ranks ----------------
__global__ void k_prep(const float* __restrict__ sx, const float* __restrict__ sy,
                       const float* __restrict__ vpW, const float* __restrict__ vpb,
                       const float* __restrict__ age) {
    __shared__ float a_s[MEM];
    int b = blockIdx.x, tid = threadIdx.x;
    if (b < 128) {
        int idx = b * 256 + tid;
        int r = idx >> 6, c = idx & 63;
        float acc = g_bias2[c];
        const float* xr = sx + (size_t)r * DIN;
        for (int k = 0; k < DIN; k++) acc += xr[k] * g_bWkp[k * KEY + c];
        g_proj_keys[idx] = acc;
    } else if (b < 384) {
        int idx = (b - 128) * 256 + tid;
        int r = idx >> 7, c = idx & 127;
        float acc = vpb[c];
        const float* yr = sy + (size_t)r * VAL;
        for (int k = 0; k < VAL; k++) acc += yr[k] * vpW[k * VAL + c];
        g_proj_vals[idx] = acc;
    } else {
        for (int i = tid; i < MEM; i += 256) a_s[i] = age[i];
        __syncthreads();
        int j = (b - 384) * 256 + tid;
        if (j < MEM) {
            float aj = a_s[j];
            int cnt = 0;
            for (int i = 0; i < MEM; i++) {
                float ai = a_s[i];
                cnt += (ai > aj) || (ai == aj && i < j);
            }
            g_rank[j] = cnt;
        }
    }
}

// ---------------- scatter + pre-split into bf16 hi/lo planes ----------------
__global__ void k_scatter(const float* __restrict__ mk, const float* __restrict__ mv) {
    int j = blockIdx.x;            // 0..NSLOT-1
    int t = threadIdx.x;           // 192
    int ch = j >> 6, sp = (j & 63) >> 1, half = j & 1;
    if (j >= MEM) {                // padded rows: zero planes
        if (t < 32) { g_khi[j * 32 + t] = 0u; g_klo[j * 32 + t] = 0u; }
        else if (t >= 64) {
            int c = t - 64;
            __nv_bfloat16 z = __float2bfloat16_rn(0.f);
            ((__nv_bfloat16*)&g_vhi[((size_t)ch * 128 + c) * 32 + sp])[half] = z;
            ((__nv_bfloat16*)&g_vlo[((size_t)ch * 128 + c) * 32 + sp])[half] = z;
        }
        return;
    }
    int r = g_rank[j];
    if (t < 32) {                  // key pair t -> hi/lo planes
        const float* src = (r < BSS) ? &g_proj_keys[r * KEY] : &mk[(size_t)j * KEY];
        float2 v = *(const float2*)&src[t * 2];
        u32 hi, lo; split2(v.x, v.y, hi, lo);
        g_khi[j * 32 + t] = hi; g_klo[j * 32 + t] = lo;
    } else if (t >= 64) {          // value col c -> transposed planes (byte-granular)
        int c = t - 64;
        float v = (r < BSS) ? g_proj_vals[r * VAL + c] : mv[(size_t)j * VAL + c];
        __nv_bfloat16 hb = __float2bfloat16_rn(v);
        __nv_bfloat16 lb = __float2bfloat16_rn(v - __bfloat162float(hb));
        ((__nv_bfloat16*)&g_vhi[((size_t)ch * 128 + c) * 32 + sp])[half] = hb;
        ((__nv_bfloat16*)&g_vlo[((size_t)ch * 128 + c) * 32 + sp])[half] = lb;
    }
}

// ---------------- qfeat: 128-row blocks, 512 thr, cp.async double-buffered ----------------
#define QF_AS 0                         /* [2][128*68] = 17408 */
#define QF_BC 17408                     /* [2][64*64]  = 8192  */
#define QF_KP 25600                     /* [64][64]    = 4096  */
#define QF_SMEM_FLOATS 29696
__global__ void __launch_bounds__(512) k_qfeat(
        const float* __restrict__ qx, const float* __restrict__ bW,
        const float* __restrict__ bb, const float* __restrict__ kpW,
        const float* __restrict__ kpb) {
    extern __shared__ float sm[];
    float* A_s  = sm + QF_AS;     // [2][128r][68]
    float* Bc   = sm + QF_BC;     // [2][64k][64c]
    float* kp_s = sm + QF_KP;     // [64][64]
    int tid = threadIdx.x;
    int tx = tid & 15, ty = tid >> 4;      // ty 0..31 -> rows ty*4..+3
    int row0 = blockIdx.x * 128;

    u32 aA = (u32)__cvta_generic_to_shared(A_s);
    u32 bA = (u32)__cvta_generic_to_shared(Bc);

    for (int i = tid; i < KEY * KEY / 4; i += 512)
        ((float4*)kp_s)[i] = ((const float4*)kpW)[i];

    // async stage of chunk kc into buffer b: A rows (coalesced f4) + Bc
    auto issue = [&](int kc, int b) {
#pragma unroll
        for (int rep = 0; rep < 4; rep++) {           // A: 2048 f4
            int i = tid + rep * 512;
            int r = i >> 4, q4 = i & 15;
            cp16(aA + (u32)((b * 8704 + r * 68 + q4 * 4) * 4),
                 qx + (size_t)(row0 + r) * DIN + kc * 64 + q4 * 4);
        }
#pragma unroll
        for (int rep = 0; rep < 2; rep++) {           // Bc: 1024 f4
            int i = tid + rep * 512;
            cp16(bA + (u32)((b * 4096 + i * 4) * 4),
                 bW + kc * 4096 + i * 4);
        }
        CP_COMMIT();
    };

    u64 acc[4][2];
#pragma unroll
    for (int i = 0; i < 4; i++) { acc[i][0] = 0ULL; acc[i][1] = 0ULL; }

    issue(0, 0);
    for (int kc = 0; kc < DIN / 64; kc++) {
        int buf = kc & 1;
        if (kc + 1 < DIN / 64) { issue(kc + 1, buf ^ 1); CP_WAIT(1); }
        else                   { CP_WAIT(0); }
        __syncthreads();
        const float* Ab = A_s + buf * 8704;
        const float* Bb = Bc + buf * 4096;
#pragma unroll 4
        for (int k4 = 0; k4 < 64; k4 += 4) {
            float4 av[4];
#pragma unroll
            for (int i = 0; i < 4; i++)
                av[i] = *(const float4*)&Ab[(ty * 4 + i) * 68 + k4];
#pragma unroll
            for (int kk = 0; kk < 4; kk++) {
                ulonglong2 b2 = *(const ulonglong2*)&Bb[(k4 + kk) * 64 + tx * 4];
#pragma unroll
                for (int i = 0; i < 4; i++) {
                    float a = (kk == 0) ? av[i].x : (kk == 1) ? av[i].y
                            : (kk == 2) ? av[i].z : av[i].w;
                    u64 a2; PACKF_F32X2(a2, a, a);
                    FMA_F32X2(acc[i][0], a2, b2.x, acc[i][0]);
                    FMA_F32X2(acc[i][1], a2, b2.y, acc[i][1]);
                }
            }
        }
        __syncthreads();   // all reads of buf done before it is re-staged
    }
    float* feat_s = A_s;   // buffer 0 reused as feat tile [128][68]
    float4 bias = *(const float4*)&bb[tx * 4];
#pragma unroll
    for (int i = 0; i < 4; i++) {
        int r = ty * 4 + i;
        float v0, v1, v2, v3;
        UNPACKF_F32X2(v0, v1, acc[i][0]);
        UNPACKF_F32X2(v2, v3, acc[i][1]);
        float4 v = make_float4(v0 + bias.x, v1 + bias.y, v2 + bias.z, v3 + bias.w);
        *(float4*)&feat_s[r * 68 + tx * 4] = v;
        *(float4*)&g_query_feat[(size_t)(row0 + r) * KEY + tx * 4] = v;
    }
    __syncthreads();

    // proj_q = feat @ kp_W + kp_b
    u64 acc2[4][2];
#pragma unroll
    for (int i = 0; i < 4; i++) { acc2[i][0] = 0ULL; acc2[i][1] = 0ULL; }
#pragma unroll 4
    for (int k4 = 0; k4 < KEY; k4 += 4) {
        float4 av[4];
#pragma unroll
        for (int i = 0; i < 4; i++)
            av[i] = *(const float4*)&feat_s[(ty * 4 + i) * 68 + k4];
#pragma unroll
        for (int kk = 0; kk < 4; kk++) {
            ulonglong2 b2 = *(const ulonglong2*)&kp_s[(k4 + kk) * KEY + tx * 4];
#pragma unroll
            for (int i = 0; i < 4; i++) {
                float a = (kk == 0) ? av[i].x : (kk == 1) ? av[i].y
                        : (kk == 2) ? av[i].z : av[i].w;
                u64 a2; PACKF_F32X2(a2, a, a);
                FMA_F32X2(acc2[i][0], a2, b2.x, acc2[i][0]);
                FMA_F32X2(acc2[i][1], a2, b2.y, acc2[i][1]);
            }
        }
    }
    float4 kb = *(const float4*)&kpb[tx * 4];
#pragma unroll
    for (int i = 0; i < 4; i++) {
        int r = ty * 4 + i;
        float v0, v1, v2, v3;
        UNPACKF_F32X2(v0, v1, acc2[i][0]);
        UNPACKF_F32X2(v2, v3, acc2[i][1]);
        float4 v = make_float4(v0 + kb.x, v1 + kb.y, v2 + kb.z, v3 + kb.w);
        *(float4*)&g_proj_q[(size_t)(row0 + r) * KEY + tx * 4] = v;
    }
}

// ---------------- flash attention: tensor cores + cp.async + packed-W exp ----------------
#define AT_QHI 0
#define AT_QLO (AT_QHI + 128 * 36)
#define AT_KHI (AT_QLO + 128 * 36)          /* [2][64*36]  */
#define AT_KLO (AT_KHI + 2 * 64 * 36)
#define AT_VHI (AT_KLO + 2 * 64 * 36)       /* [2][128*36] */
#define AT_VLO (AT_VHI + 2 * 128 * 36)
#define AT_WS  (AT_VLO + 2 * 128 * 36)      /* [64 s][132 r] f32 scores */
#define AT_WPH (AT_WS + 64 * 132)           /* [128 r][36] packed W hi  */
#define AT_WPL (AT_WPH + 128 * 36)          /* [128 r][36] packed W lo  */
#define AT_SC  (AT_WPL + 128 * 36)
#define AT_LI  (AT_SC + 128)
#define AT_SMEM_FLOATS (AT_LI + 128)
__global__ void __launch_bounds__(512) k_attn(float* __restrict__ outR) {
    extern __shared__ float sm[];
    u32*  QHI = (u32*)sm + AT_QHI;
    u32*  QLO = (u32*)sm + AT_QLO;
    u32*  KHI = (u32*)sm + AT_KHI;
    u32*  KLO = (u32*)sm + AT_KLO;
    u32*  VHI = (u32*)sm + AT_VHI;
    u32*  VLO = (u32*)sm + AT_VLO;
    float* ws = sm + AT_WS;
    u32*  WPH = (u32*)sm + AT_WPH;
    u32*  WPL = (u32*)sm + AT_WPL;
    float* sc = sm + AT_SC;
    float* li = sm + AT_LI;
    int tid = threadIdx.x;
    int lane = tid & 31, w = tid >> 5;
    int g = lane >> 2, t = lane & 3;
    int r_e = tid >> 2, h = tid & 3;
    int row0 = blockIdx.x * 128;

    u32 khiA = (u32)__cvta_generic_to_shared(KHI);
    u32 kloA = (u32)__cvta_generic_to_shared(KLO);
    u32 vhiA = (u32)__cvta_generic_to_shared(VHI);
    u32 vloA = (u32)__cvta_generic_to_shared(VLO);

    // stage Q hi/lo planes (once per block)
    for (int i = tid; i < 128 * 32; i += 512) {
        int r = i >> 5, p = i & 31;
        float2 v = *(const float2*)&g_proj_q[(size_t)(row0 + r) * KEY + p * 2];
        u32 hi, lo; split2(v.x, v.y, hi, lo);
        QHI[r * 36 + p] = hi; QLO[r * 36 + p] = lo;
    }

    int mt2 = w & 7, nb2 = (w >> 3) * 8;
    float acc[8][4];
#pragma unroll
    for (int nt = 0; nt < 8; nt++)
#pragma unroll
        for (int p = 0; p < 4; p++) acc[nt][p] = 0.f;
    float m = -1e30f, l = 0.f;

    auto issue = [&](int ch, int b) {
        int m0 = ch * 64;
        {   // K planes
            int s = tid >> 3, p4 = tid & 7;
            u32 off = (u32)((b * 64 * 36 + s * 36 + p4 * 4) * 4);
            cp16(khiA + off, g_khi + (size_t)(m0 + s) * 32 + p4 * 4);
            cp16(kloA + off, g_klo + (size_t)(m0 + s) * 32 + p4 * 4);
        }
#pragma unroll
        for (int rep = 0; rep < 2; rep++) {   // V planes
            int i = tid + rep * 512;
            int c = i >> 3, p4 = i & 7;
            u32 off = (u32)((b * 128 * 36 + c * 36 + p4 * 4) * 4);
            const size_t gsrc = (size_t)ch * 4096 + c * 32 + p4 * 4;
            cp16(vhiA + off, g_vhi + gsrc);
            cp16(vloA + off, g_vlo + gsrc);
        }
        CP_COMMIT();
    };

    issue(0, 0);

    for (int ch = 0; ch < NSLOT / 64; ch++) {
        int m0 = ch * 64;
        int buf = ch & 1;
        __syncthreads();
        if (ch + 1 < NSLOT / 64) { issue(ch + 1, buf ^ 1); CP_WAIT(1); }
        else                     { CP_WAIT(0); }
        __syncthreads();

        const u32* KHIb = KHI + buf * 64 * 36;
        const u32* KLOb = KLO + buf * 64 * 36;
        const u32* VHIb = VHI + buf * 128 * 36;
        const u32* VLOb = VLO + buf * 128 * 36;

        // ---- GEMM1: warp w -> m-tile (w&3), n-tiles (w>>2)*4 .. +3 ----
        {
            int mt = w & 3, ntb = (w >> 2) * 4;
            int s0 = mt * 16 + g;
            u32 ahi[4][4], alo[4][4];
#pragma unroll
            for (int kt = 0; kt < 4; kt++) {
                int b0 = s0 * 36 + 8 * kt + t, b1 = (s0 + 8) * 36 + 8 * kt + t;
                ahi[kt][0] = KHIb[b0]; ahi[kt][1] = KHIb[b1];
                ahi[kt][2] = KHIb[b0 + 4]; ahi[kt][3] = KHIb[b1 + 4];
                alo[kt][0] = KLOb[b0]; alo[kt][1] = KLOb[b1];
                alo[kt][2] = KLOb[b0 + 4]; alo[kt][3] = KLOb[b1 + 4];
            }
#pragma unroll
            for (int ntl = 0; ntl < 4; ntl++) {
                int qb = (ntb + ntl) * 8;
                float d[4] = {0.f, 0.f, 0.f, 0.f};
#pragma unroll
                for (int kt = 0; kt < 4; kt++) {
                    int bb = (qb + g) * 36 + 8 * kt + t;
                    u32 bh0 = QHI[bb], bh1 = QHI[bb + 4];
                    u32 bl0 = QLO[bb], bl1 = QLO[bb + 4];
                    MMA_BF16(d, ahi[kt], bh0, bh1);
                    MMA_BF16(d, ahi[kt], bl0, bl1);
                    MMA_BF16(d, alo[kt], bh0, bh1);
                }
                int rw = qb + t * 2;
                *(float2*)&ws[s0 * 132 + rw]       = make_float2(d[0], d[1]);
                *(float2*)&ws[(s0 + 8) * 132 + rw] = make_float2(d[2], d[3]);
            }
        }
        __syncthreads();

        // ---- exp phase: row r_e, slot pairs {4q+h} -> packed bf16 W planes ----
        {
            int lim = MEM - m0;
            float raw[8][2];
            float mx = -1e30f;
#pragma unroll
            for (int q = 0; q < 8; q++) {
                int s0 = q * 8 + 2 * h;
                float v0 = ws[s0 * 132 + r_e];
                float v1 = ws[(s0 + 1) * 132 + r_e];
                raw[q][0] = v0; raw[q][1] = v1;
                if (s0 < lim && v0 > mx) mx = v0;
                if (s0 + 1 < lim && v1 > mx) mx = v1;
            }
            mx = fmaxf(mx, __shfl_xor_sync(0xffffffffu, mx, 1));
            mx = fmaxf(mx, __shfl_xor_sync(0xffffffffu, mx, 2));
            float mnew = fmaxf(m, mx);
            float scl = __expf(m - mnew);
            float ls = 0.f;
#pragma unroll
            for (int q = 0; q < 8; q++) {
                int s0 = q * 8 + 2 * h;
                float w0 = (s0     < lim) ? __expf(raw[q][0] - mnew) : 0.f;
                float w1 = (s0 + 1 < lim) ? __expf(raw[q][1] - mnew) : 0.f;
                ls += w0 + w1;
                u32 hi, lo; split2(w0, w1, hi, lo);
                WPH[r_e * 36 + q * 4 + h] = hi;
                WPL[r_e * 36 + q * 4 + h] = lo;
            }
            ls += __shfl_xor_sync(0xffffffffu, ls, 1);
            ls += __shfl_xor_sync(0xffffffffu, ls, 2);
            l = l * scl + ls;
            m = mnew;
            if (h == 0) sc[r_e] = scl;
        }
        __syncthreads();

        // ---- GEMM2: rows mt2*16+g(+8), n-tiles nb2..nb2+7 ----
        {
            int r0 = mt2 * 16 + g, r1 = r0 + 8;
            float s0f = sc[r0], s1f = sc[r1];
#pragma unroll
            for (int nt = 0; nt < 8; nt++) {
                acc[nt][0] *= s0f; acc[nt][1] *= s0f;
                acc[nt][2] *= s1f; acc[nt][3] *= s1f;
            }
            u32 ahi[4][4], alo[4][4];
#pragma unroll
            for (int kt = 0; kt < 4; kt++) {
                int p0 = kt * 8 + t;
                ahi[kt][0] = WPH[r0 * 36 + p0];     ahi[kt][1] = WPH[r1 * 36 + p0];
                ahi[kt][2] = WPH[r0 * 36 + p0 + 4]; ahi[kt][3] = WPH[r1 * 36 + p0 + 4];
                alo[kt][0] = WPL[r0 * 36 + p0];     alo[kt][1] = WPL[r1 * 36 + p0];
                alo[kt][2] = WPL[r0 * 36 + p0 + 4]; alo[kt][3] = WPL[r1 * 36 + p0 + 4];
            }
#pragma unroll
            for (int nt = 0; nt < 8; nt++) {
                int cb = ((nb2 + nt) * 8 + g) * 36;
#pragma unroll
                for (int kt = 0; kt < 4; kt++) {
                    int bb = cb + 8 * kt + t;
                    u32 bh0 = VHIb[bb], bh1 = VHIb[bb + 4];
                    u32 bl0 = VLOb[bb], bl1 = VLOb[bb + 4];
                    MMA_BF16(acc[nt], ahi[kt], bh0, bh1);
                    MMA_BF16(acc[nt], ahi[kt], bl0, bl1);
                    MMA_BF16(acc[nt], alo[kt], bh0, bh1);
                }
            }
        }
    }

    if (h == 0) li[r_e] = 1.0f / l;
    __syncthreads();

    // epilogue: normalize + scalar stores (out only 4B-aligned)
    {
        int r0 = mt2 * 16 + g, r1 = r0 + 8;
        float li0 = li[r0], li1 = li[r1];
        float* op0 = outR + (size_t)(row0 + r0) * VAL;
        float* op1 = outR + (size_t)(row0 + r1) * VAL;
#pragma unroll
        for (int nt = 0; nt < 8; nt++) {
            int c = (nb2 + nt) * 8 + t * 2;
            op0[c]     = acc[nt][0] * li0;
            op0[c + 1] = acc[nt][1] * li0;
            op1[c]     = acc[nt][2] * li1;
            op1[c + 1] = acc[nt][3] * li1;
        }
    }
}

// ---------------- fused controller MLP: W1 streamed in 4 chunks -> 2 CTAs/SM ----------------
#define MLP_W1C 0                       /* [48][128] = 6144 floats; h2 aliases */
#define MLP_AUG 6144                    /* [64][193] */
#define MLP_H1  (6144 + 64 * 193)       /* [64][129] */
#define MLP_RED (MLP_H1 + 64 * 129)     /* [64] */
#define MLP_SMEM_FLOATS (MLP_RED + 64)
__global__ void __launch_bounds__(256) k_mlp(
        const float* __restrict__ qy, const float* retrIn, float* predOut,
        const float* __restrict__ W1, const float* __restrict__ b1,
        const float* __restrict__ W2, const float* __restrict__ b2,
        const float* __restrict__ W3, const float* __restrict__ b3) {
    extern __shared__ float sm[];
    float* W1c   = sm + MLP_W1C;
    float* aug_s = sm + MLP_AUG;
    float* h1_s  = sm + MLP_H1;
    float* red   = sm + MLP_RED;
    float* h2_s  = sm + MLP_W1C;        // alias: W1c dead after h1
    float* W2_s  = aug_s;               // alias: aug dead after h1
    int tid = threadIdx.x;
    int row0 = blockIdx.x * 64;

    for (int i = tid; i < 64 * 192; i += 256) {
        int r = i / 192, c = i % 192;
        float v = (c < KEY) ? g_query_feat[(row0 + r) * KEY + c]
                            : retrIn[(size_t)(row0 + r) * VAL + (c - KEY)];
        aug_s[r * 193 + c] = v;
    }

    {   // h1 = relu(aug @ W1 + b1); W1 streamed in 4 k-chunks of 48
        int r = tid & 63, g = tid >> 6;
        u64 acc[16];
#pragma unroll
        for (int c = 0; c < 16; c++) {
            float x = b1[g * 32 + 2 * c], y = b1[g * 32 + 2 * c + 1];
            PACKF_F32X2(acc[c], x, y);
        }
        for (int kc = 0; kc < 4; kc++) {
            __syncthreads();
            for (int i = tid; i < 48 * 128 / 4; i += 256)
                ((float4*)W1c)[i] = ((const float4*)(W1 + kc * 48 * 128))[i];
            __syncthreads();
            for (int k = 0; k < 48; k++) {
                float a = aug_s[r * 193 + kc * 48 + k];
                u64 a2; PACKF_F32X2(a2, a, a);
                const ulonglong2* wr = (const ulonglong2*)(W1c + k * 128 + g * 32);
#pragma unroll
                for (int q = 0; q < 8; q++) {
                    ulonglong2 wv = wr[q];
                    FMA_F32X2(acc[2 * q],     a2, wv.x, acc[2 * q]);
                    FMA_F32X2(acc[2 * q + 1], a2, wv.y, acc[2 * q + 1]);
                }
            }
        }
#pragma unroll
        for (int c = 0; c < 16; c++) {
            float x, y;
            UNPACKF_F32X2(x, y, acc[c]);
            h1_s[r * 129 + g * 32 + 2 * c]     = fmaxf(x, 0.f);
            h1_s[r * 129 + g * 32 + 2 * c + 1] = fmaxf(y, 0.f);
        }
    }
    __syncthreads();
    for (int i = tid; i < 128 * 64 / 4; i += 256)
        ((float4*)W2_s)[i] = ((const float4*)W2)[i];
    __syncthreads();

    {   // h2 = relu(h1 @ W2 + b2)
        int r = tid & 63, g = tid >> 6;
        u64 acc[8];
#pragma unroll
        for (int c = 0; c < 8; c++) {
            float x = b2[g * 16 + 2 * c], y = b2[g * 16 + 2 * c + 1];
            PACKF_F32X2(acc[c], x, y);
        }
        for (int k = 0; k < 128; k++) {
            float a = h1_s[r * 129 + k];
            u64 a2; PACKF_F32X2(a2, a, a);
            const ulonglong2* wr = (const ulonglong2*)(W2_s + k * 64 + g * 16);
#pragma unroll
            for (int q = 0; q < 4; q++) {
                ulonglong2 wv = wr[q];
                FMA_F32X2(acc[2 * q],     a2, wv.x, acc[2 * q]);
                FMA_F32X2(acc[2 * q + 1], a2, wv.y, acc[2 * q + 1]);
            }
        }
#pragma unroll
        for (int c = 0; c < 8; c++) {
            float x, y;
            UNPACKF_F32X2(x, y, acc[c]);
            h2_s[r * 65 + g * 16 + 2 * c]     = fmaxf(x, 0.f);
            h2_s[r * 65 + g * 16 + 2 * c + 1] = fmaxf(y, 0.f);
        }
    }
    __syncthreads();
    {   // pred = h2 @ W3 + b3 ; squared error partial
        int r = tid >> 2, g = tid & 3;
        float s = 0.f;
#pragma unroll
        for (int i = 0; i < 16; i++) s += h2_s[r * 65 + g * 16 + i] * W3[g * 16 + i];
        s += __shfl_xor_sync(0xffffffffu, s, 1);
        s += __shfl_xor_sync(0xffffffffu, s, 2);
        if (g == 0) {
            float p = s + b3[0];
            predOut[row0 + r] = p;
            float d = p - qy[row0 + r];
            red[r] = d * d;
        }
    }
    __syncthreads();
    if (tid < 32) {
        float v = red[tid] + red[tid + 32];
        v += __shfl_xor_sync(0xffffffffu, v, 16);
        v += __shfl_xor_sync(0xffffffffu, v, 8);
        v += __shfl_xor_sync(0xffffffffu, v, 4);
        v += __shfl_xor_sync(0xffffffffu, v, 2);
        v += __shfl_xor_sync(0xffffffffu, v, 1);
        if (tid == 0) g_loss_part[blockIdx.x] = v;
    }
}

// ---------------- deterministic loss finalize ----------------
__global__ void k_finalize(float* __restrict__ out) {
    __shared__ float s[1024];
    int t = threadIdx.x;
    s[t] = g_loss_part[t];
    __syncthreads();
    for (int st = 512; st > 0; st >>= 1) {
        if (t < st) s[t] += s[t + st];
        __syncthreads();
    }
    if (t == 0) out[0] = s[0] / (float)BQ;
}

// ---------------- launcher ----------------
extern "C" void kernel_launch(void* const* d_in, const int* in_sizes, int n_in,
                              void* d_out, int out_size) {
    const float* support_x  = (const float*)d_in[0];
    const float* support_y  = (const float*)d_in[1];
    const float* query_x    = (const float*)d_in[2];
    const float* query_y    = (const float*)d_in[3];
    const float* base_W     = (const float*)d_in[4];
    const float* base_b     = (const float*)d_in[5];
    const float* kp_W       = (const float*)d_in[6];
    const float* kp_b       = (const float*)d_in[7];
    const float* vp_W       = (const float*)d_in[8];
    const float* vp_b       = (const float*)d_in[9];
    const float* mem_keys   = (const float*)d_in[10];
    const float* mem_values = (const float*)d_in[11];
    const float* mem_age    = (const float*)d_in[12];
    const float* c1_W       = (const float*)d_in[13];
    const float* c1_b       = (const float*)d_in[14];
    const float* c2_W       = (const float*)d_in[15];
    const float* c2_b       = (const float*)d_in[16];
    const float* c3_W       = (const float*)d_in[17];
    const float* c3_b       = (const float*)d_in[18];
    float* out = (float*)d_out;

    float *p_pred_fb, *p_retr_fb;
    cudaGetSymbolAddress((void**)&p_pred_fb, g_pred_fb);
    cudaGetSymbolAddress((void**)&p_retr_fb, g_retr_fb);

    float* predBuf = (out_size >= 1 + BQ)            ? out + 1      : p_pred_fb;
    float* retrBuf = (out_size >= 1 + BQ + BQ * VAL) ? out + 1 + BQ : p_retr_fb;

    const int qf_smem  = QF_SMEM_FLOATS * 4;
    const int at_smem  = AT_SMEM_FLOATS * 4;
    const int mlp_smem = MLP_SMEM_FLOATS * 4;
    cudaFuncSetAttribute(k_qfeat, cudaFuncAttributeMaxDynamicSharedMemorySize, qf_smem);
    cudaFuncSetAttribute(k_attn,  cudaFuncAttributeMaxDynamicSharedMemorySize, at_smem);
    cudaFuncSetAttribute(k_mlp,   cudaFuncAttributeMaxDynamicSharedMemorySize, mlp_smem);

    // launch order arranged so k_qfeat is the 4th launch (ncu -s window)
    k_fuse<<<8, 256>>>(base_W, base_b, kp_W, kp_b);
    k_prep<<<388, 256>>>(support_x, support_y, vp_W, vp_b, mem_age);
    k_scatter<<<NSLOT, 192>>>(mem_keys, mem_values);
    k_qfeat<<<BQ / 128, 512, qf_smem>>>(query_x, base_W, base_b, kp_W, kp_b);
    k_attn<<<BQ / 128, 512, at_smem>>>(retrBuf);
    k_mlp<<<BQ / 64, 256, mlp_smem>>>(query_y, retrBuf, predBuf,
                                      c1_W, c1_b, c2_W, c2_b, c3_W, c3_b);
    k_finalize<<<1, 1024>>>(out);
}

// round 17
// speedup vs baseline: 1.0508x; 1.0508x over previous
#include <cuda_runtime.h>
#include <cuda_bf16.h>

#define MEM   1000
#define NSLOT 1024          /* padded slot count (rows 1000..1023 zero) */
#define KEY   64
#define VAL   128
#define DIN   512
#define BSS   512
#define BQ    65536

typedef unsigned long long u64;
typedef unsigned int u32;

// ---------------- packed f32x2 helpers (Blackwell sm_103a) ----------------
#define PACKF_F32X2(out, a, b) \
    asm("mov.b64 %0, {%1, %2};" : "=l"(out) : "f"(a), "f"(b))
#define UNPACKF_F32X2(a, b, in) \
    asm("mov.b64 {%0, %1}, %2;" : "=f"(a), "=f"(b) : "l"(in))
#define FMA_F32X2(d, a, b, c) \
    asm("fma.rn.f32x2 %0, %1, %2, %3;" : "=l"(d) : "l"(a), "l"(b), "l"(c))

// ---------------- bf16 HMMA m16n8k16 ----------------
#define MMA_BF16(d, a, b0, b1) \
    asm volatile("mma.sync.aligned.m16n8k16.row.col.f32.bf16.bf16.f32 " \
        "{%0,%1,%2,%3}, {%4,%5,%6,%7}, {%8,%9}, {%0,%1,%2,%3};" \
        : "+f"((d)[0]), "+f"((d)[1]), "+f"((d)[2]), "+f"((d)[3]) \
        : "r"((a)[0]), "r"((a)[1]), "r"((a)[2]), "r"((a)[3]), "r"(b0), "r"(b1))

// split x,y into hi/lo bf16 pairs (packed b32; low half = first element)
__device__ __forceinline__ void split2(float x, float y, u32& hi, u32& lo) {
    __nv_bfloat16 hx = __float2bfloat16_rn(x), hy = __float2bfloat16_rn(y);
    __nv_bfloat16 lx = __float2bfloat16_rn(x - __bfloat162float(hx));
    __nv_bfloat16 ly = __float2bfloat16_rn(y - __bfloat162float(hy));
    __nv_bfloat162 H = __halves2bfloat162(hx, hy);
    __nv_bfloat162 L = __halves2bfloat162(lx, ly);
    hi = *reinterpret_cast<u32*>(&H);
    lo = *reinterpret_cast<u32*>(&L);
}

// cp.async 16B copy
__device__ __forceinline__ void cp16(u32 dst_smem, const void* src) {
    asm volatile("cp.async.ca.shared.global [%0], [%1], 16;" :: "r"(dst_smem), "l"(src));
}
#define CP_COMMIT() asm volatile("cp.async.commit_group;")
#define CP_WAIT(n)  asm volatile("cp.async.wait_group %0;" :: "n"(n))

// ---------------- device scratch (no allocations allowed) ----------------
__device__ __align__(16) float g_proj_keys[BSS * KEY];
__device__ __align__(16) float g_proj_vals[BSS * VAL];
__device__             int   g_rank[MEM];
// pre-split bf16 hi/lo planes (built once in k_scatter)
__device__ __align__(16) u32 g_khi[NSLOT * 32];            // [slot][key-pair]
__device__ __align__(16) u32 g_klo[NSLOT * 32];
__device__ __align__(16) u32 g_vhi[16 * 128 * 32];         // [chunk][col][slot-pair]
__device__ __align__(16) u32 g_vlo[16 * 128 * 32];
__device__ __align__(16) float g_query_feat[BQ * KEY];
__device__ __align__(16) float g_proj_q[BQ * KEY];
__device__ __align__(16) float g_retr_fb[BQ * VAL];
__device__ __align__(16) float g_pred_fb[BQ];
__device__             float g_loss_part[BQ / 64];

// ---------------- prep: proj_keys (sf->pk row-local), proj_vals, ranks ----------------
__global__ void k_prep(const float* __restrict__ sx, const float* __restrict__ sy,
                       const float* __restrict__ bW, const float* __restrict__ bb,
                       const float* __restrict__ kpW, const float* __restrict__ kpb,
                       const float* __restrict__ vpW, const float* __restrict__ vpb,
                       const float* __restrict__ age) {
    __shared__ float shmem[KEY * KEY + 4 * KEY];   // kp_s + sf rows (reused as a_s)
    int b = blockIdx.x, tid = threadIdx.x;         // 256 threads
    if (b < 128) {
        // 4 support rows per block: sf = sx@bW + bb ; pk = sf@kpW + kpb
        float* kp_s = shmem;
        float* sf   = shmem + KEY * KEY;           // [4][64]
        for (int i = tid; i < KEY * KEY / 4; i += 256)
            ((float4*)kp_s)[i] = ((const float4*)kpW)[i];
        int rl = tid >> 6, c = tid & 63;
        int r = b * 4 + rl;
        float acc = bb[c];
        const float* xr = sx + (size_t)r * DIN;
        for (int k = 0; k < DIN; k++) acc += xr[k] * bW[k * KEY + c];
        sf[rl * 64 + c] = acc;
        __syncthreads();
        float acc2 = kpb[c];
        for (int k = 0; k < KEY; k++) acc2 += sf[rl * 64 + k] * kp_s[k * 64 + c];
        g_proj_keys[r * KEY + c] = acc2;
    } else if (b < 384) {
        int idx = (b - 128) * 256 + tid;
        int r = idx >> 7, c = idx & 127;
        float acc = vpb[c];
        const float* yr = sy + (size_t)r * VAL;
        for (int k = 0; k < VAL; k++) acc += yr[k] * vpW[k * VAL + c];
        g_proj_vals[idx] = acc;
    } else {
        float* a_s = shmem;                        // reuse for ages
        for (int i = tid; i < MEM; i += 256) a_s[i] = age[i];
        __syncthreads();
        int j = (b - 384) * 256 + tid;
        if (j < MEM) {
            float aj = a_s[j];
            int cnt = 0;
            for (int i = 0; i < MEM; i++) {
                float ai = a_s[i];
                cnt += (ai > aj) || (ai == aj && i < j);
            }
            g_rank[j] = cnt;
        }
    }
}

// ---------------- scatter + pre-split into bf16 hi/lo planes ----------------
__global__ void k_scatter(const float* __restrict__ mk, const float* __restrict__ mv) {
    int j = blockIdx.x;            // 0..NSLOT-1
    int t = threadIdx.x;           // 192
    int ch = j >> 6, sp = (j & 63) >> 1, half = j & 1;
    if (j >= MEM) {                // padded rows: zero planes
        if (t < 32) { g_khi[j * 32 + t] = 0u; g_klo[j * 32 + t] = 0u; }
        else if (t >= 64) {
            int c = t - 64;
            __nv_bfloat16 z = __float2bfloat16_rn(0.f);
            ((__nv_bfloat16*)&g_vhi[((size_t)ch * 128 + c) * 32 + sp])[half] = z;
            ((__nv_bfloat16*)&g_vlo[((size_t)ch * 128 + c) * 32 + sp])[half] = z;
        }
        return;
    }
    int r = g_rank[j];
    if (t < 32) {                  // key pair t -> hi/lo planes
        const float* src = (r < BSS) ? &g_proj_keys[r * KEY] : &mk[(size_t)j * KEY];
        float2 v = *(const float2*)&src[t * 2];
        u32 hi, lo; split2(v.x, v.y, hi, lo);
        g_khi[j * 32 + t] = hi; g_klo[j * 32 + t] = lo;
    } else if (t >= 64) {          // value col c -> transposed planes (byte-granular)
        int c = t - 64;
        float v = (r < BSS) ? g_proj_vals[r * VAL + c] : mv[(size_t)j * VAL + c];
        __nv_bfloat16 hb = __float2bfloat16_rn(v);
        __nv_bfloat16 lb = __float2bfloat16_rn(v - __bfloat162float(hb));
        ((__nv_bfloat16*)&g_vhi[((size_t)ch * 128 + c) * 32 + sp])[half] = hb;
        ((__nv_bfloat16*)&g_vlo[((size_t)ch * 128 + c) * 32 + sp])[half] = lb;
    }
}

// ---------------- fused: query_feat ; proj_q — 128-row blocks, f32x2, float4 a-loads ----------------
#define QF_AS 0                       /* [128][68] = 8704  */
#define QF_BC 8704                    /* [64][64]  = 4096  */
#define QF_KP 12800                   /* [64][64]  = 4096  */
#define QF_SMEM_FLOATS 16896
__global__ void __launch_bounds__(256) k_qfeat(
        const float* __restrict__ qx, const float* __restrict__ bW,
        const float* __restrict__ bb, const float* __restrict__ kpW,
        const float* __restrict__ kpb) {
    extern __shared__ float sm[];
    float* A_s  = sm + QF_AS;     // [128r][68]
    float* Bc   = sm + QF_BC;     // [64k][64c] current chunk of base_W
    float* kp_s = sm + QF_KP;     // [64][64]
    int tid = threadIdx.x;
    int tx = tid & 15, ty = tid >> 4;      // ty 0..15 -> rows ty*8..+7
    int row0 = blockIdx.x * 128;

    for (int i = tid; i < KEY * KEY / 4; i += 256)
        ((float4*)kp_s)[i] = ((const float4*)kpW)[i];

    u64 acc[8][2];
#pragma unroll
    for (int i = 0; i < 8; i++) { acc[i][0] = 0ULL; acc[i][1] = 0ULL; }

    for (int kc = 0; kc < DIN / 64; kc++) {
        __syncthreads();
        for (int i = tid; i < 1024; i += 256)          // Bc chunk
            ((float4*)Bc)[i] = ((const float4*)(bW + kc * 4096))[i];
        for (int i = tid; i < 2048; i += 256) {        // A chunk: 128 rows x 16 f4
            int r = i >> 4, q4 = i & 15;
            *(float4*)&A_s[r * 68 + q4 * 4] =
                *(const float4*)&qx[(size_t)(row0 + r) * DIN + kc * 64 + q4 * 4];
        }
        __syncthreads();
#pragma unroll 4
        for (int k4 = 0; k4 < 64; k4 += 4) {
            float4 av[8];
#pragma unroll
            for (int i = 0; i < 8; i++)
                av[i] = *(const float4*)&A_s[(ty * 8 + i) * 68 + k4];
#pragma unroll
            for (int kk = 0; kk < 4; kk++) {
                ulonglong2 b2 = *(const ulonglong2*)&Bc[(k4 + kk) * 64 + tx * 4];
#pragma unroll
                for (int i = 0; i < 8; i++) {
                    float a = (kk == 0) ? av[i].x : (kk == 1) ? av[i].y
                            : (kk == 2) ? av[i].z : av[i].w;
                    u64 a2; PACKF_F32X2(a2, a, a);
                    FMA_F32X2(acc[i][0], a2, b2.x, acc[i][0]);
                    FMA_F32X2(acc[i][1], a2, b2.y, acc[i][1]);
                }
            }
        }
    }
    __syncthreads();  // all reads of A_s done; reuse as feat_s
    float* feat_s = A_s;
    float4 bias = *(const float4*)&bb[tx * 4];
#pragma unroll
    for (int i = 0; i < 8; i++) {
        int r = ty * 8 + i;
        float v0, v1, v2, v3;
        UNPACKF_F32X2(v0, v1, acc[i][0]);
        UNPACKF_F32X2(v2, v3, acc[i][1]);
        float4 v = make_float4(v0 + bias.x, v1 + bias.y, v2 + bias.z, v3 + bias.w);
        *(float4*)&feat_s[r * 68 + tx * 4] = v;
        *(float4*)&g_query_feat[(size_t)(row0 + r) * KEY + tx * 4] = v;
    }
    __syncthreads();

    // proj_q = feat @ kp_W + kp_b (float4 a-loads, identical FMA order)
    u64 acc2[8][2];
#pragma unroll
    for (int i = 0; i < 8; i++) { acc2[i][0] = 0ULL; acc2[i][1] = 0ULL; }
#pragma unroll 4
    for (int k4 = 0; k4 < KEY; k4 += 4) {
        float4 av[8];
#pragma unroll
        for (int i = 0; i < 8; i++)
            av[i] = *(const float4*)&feat_s[(ty * 8 + i) * 68 + k4];
#pragma unroll
        for (int kk = 0; kk < 4; kk++) {
            ulonglong2 b2 = *(const ulonglong2*)&kp_s[(k4 + kk) * KEY + tx * 4];
#pragma unroll
            for (int i = 0; i < 8; i++) {
                float a = (kk == 0) ? av[i].x : (kk == 1) ? av[i].y
                        : (kk == 2) ? av[i].z : av[i].w;
                u64 a2; PACKF_F32X2(a2, a, a);
                FMA_F32X2(acc2[i][0], a2, b2.x, acc2[i][0]);
                FMA_F32X2(acc2[i][1], a2, b2.y, acc2[i][1]);
            }
        }
    }
    float4 kb = *(const float4*)&kpb[tx * 4];
#pragma unroll
    for (int i = 0; i < 8; i++) {
        int r = ty * 8 + i;
        float v0, v1, v2, v3;
        UNPACKF_F32X2(v0, v1, acc2[i][0]);
        UNPACKF_F32X2(v2, v3, acc2[i][1]);
        float4 v = make_float4(v0 + kb.x, v1 + kb.y, v2 + kb.z, v3 + kb.w);
        *(float4*)&g_proj_q[(size_t)(row0 + r) * KEY + tx * 4] = v;
    }
}

// ---------------- flash attention: tensor cores + cp.async + packed-W exp ----------------
#define AT_QHI 0
#define AT_QLO (AT_QHI + 128 * 36)
#define AT_KHI (AT_QLO + 128 * 36)          /* [2][64*36]  */
#define AT_KLO (AT_KHI + 2 * 64 * 36)
#define AT_VHI (AT_KLO + 2 * 64 * 36)       /* [2][128*36] */
#define AT_VLO (AT_VHI + 2 * 128 * 36)
#define AT_WS  (AT_VLO + 2 * 128 * 36)      /* [64 s][132 r] f32 scores */
#define AT_WPH (AT_WS + 64 * 132)           /* [128 r][36] packed W hi  */
#define AT_WPL (AT_WPH + 128 * 36)          /* [128 r][36] packed W lo  */
#define AT_SC  (AT_WPL + 128 * 36)
#define AT_LI  (AT_SC + 128)
#define AT_SMEM_FLOATS (AT_LI + 128)
__global__ void __launch_bounds__(512) k_attn(float* __restrict__ outR) {
    extern __shared__ float sm[];
    u32*  QHI = (u32*)sm + AT_QHI;
    u32*  QLO = (u32*)sm + AT_QLO;
    u32*  KHI = (u32*)sm + AT_KHI;
    u32*  KLO = (u32*)sm + AT_KLO;
    u32*  VHI = (u32*)sm + AT_VHI;
    u32*  VLO = (u32*)sm + AT_VLO;
    float* ws = sm + AT_WS;
    u32*  WPH = (u32*)sm + AT_WPH;
    u32*  WPL = (u32*)sm + AT_WPL;
    float* sc = sm + AT_SC;
    float* li = sm + AT_LI;
    int tid = threadIdx.x;
    int lane = tid & 31, w = tid >> 5;
    int g = lane >> 2, t = lane & 3;
    int r_e = tid >> 2, h = tid & 3;
    int row0 = blockIdx.x * 128;

    u32 khiA = (u32)__cvta_generic_to_shared(KHI);
    u32 kloA = (u32)__cvta_generic_to_shared(KLO);
    u32 vhiA = (u32)__cvta_generic_to_shared(VHI);
    u32 vloA = (u32)__cvta_generic_to_shared(VLO);

    // stage Q hi/lo planes (once per block)
    for (int i = tid; i < 128 * 32; i += 512) {
        int r = i >> 5, p = i & 31;
        float2 v = *(const float2*)&g_proj_q[(size_t)(row0 + r) * KEY + p * 2];
        u32 hi, lo; split2(v.x, v.y, hi, lo);
        QHI[r * 36 + p] = hi; QLO[r * 36 + p] = lo;
    }

    int mt2 = w & 7, nb2 = (w >> 3) * 8;
    float acc[8][4];
#pragma unroll
    for (int nt = 0; nt < 8; nt++)
#pragma unroll
        for (int p = 0; p < 4; p++) acc[nt][p] = 0.f;
    float m = -1e30f, l = 0.f;

    auto issue = [&](int ch, int b) {
        int m0 = ch * 64;
        {   // K planes
            int s = tid >> 3, p4 = tid & 7;
            u32 off = (u32)((b * 64 * 36 + s * 36 + p4 * 4) * 4);
            cp16(khiA + off, g_khi + (size_t)(m0 + s) * 32 + p4 * 4);
            cp16(kloA + off, g_klo + (size_t)(m0 + s) * 32 + p4 * 4);
        }
#pragma unroll
        for (int rep = 0; rep < 2; rep++) {   // V planes
            int i = tid + rep * 512;
            int c = i >> 3, p4 = i & 7;
            u32 off = (u32)((b * 128 * 36 + c * 36 + p4 * 4) * 4);
            const size_t gsrc = (size_t)ch * 4096 + c * 32 + p4 * 4;
            cp16(vhiA + off, g_vhi + gsrc);
            cp16(vloA + off, g_vlo + gsrc);
        }
        CP_COMMIT();
    };

    issue(0, 0);

    for (int ch = 0; ch < NSLOT / 64; ch++) {
        int m0 = ch * 64;
        int buf = ch & 1;
        __syncthreads();
        if (ch + 1 < NSLOT / 64) { issue(ch + 1, buf ^ 1); CP_WAIT(1); }
        else                     { CP_WAIT(0); }
        __syncthreads();

        const u32* KHIb = KHI + buf * 64 * 36;
        const u32* KLOb = KLO + buf * 64 * 36;
        const u32* VHIb = VHI + buf * 128 * 36;
        const u32* VLOb = VLO + buf * 128 * 36;

        // ---- GEMM1: warp w -> m-tile (w&3), n-tiles (w>>2)*4 .. +3 ----
        {
            int mt = w & 3, ntb = (w >> 2) * 4;
            int s0 = mt * 16 + g;
            u32 ahi[4][4], alo[4][4];
#pragma unroll
            for (int kt = 0; kt < 4; kt++) {
                int b0 = s0 * 36 + 8 * kt + t, b1 = (s0 + 8) * 36 + 8 * kt + t;
                ahi[kt][0] = KHIb[b0]; ahi[kt][1] = KHIb[b1];
                ahi[kt][2] = KHIb[b0 + 4]; ahi[kt][3] = KHIb[b1 + 4];
                alo[kt][0] = KLOb[b0]; alo[kt][1] = KLOb[b1];
                alo[kt][2] = KLOb[b0 + 4]; alo[kt][3] = KLOb[b1 + 4];
            }
#pragma unroll
            for (int ntl = 0; ntl < 4; ntl++) {
                int qb = (ntb + ntl) * 8;
                float d[4] = {0.f, 0.f, 0.f, 0.f};
#pragma unroll
                for (int kt = 0; kt < 4; kt++) {
                    int bb = (qb + g) * 36 + 8 * kt + t;
                    u32 bh0 = QHI[bb], bh1 = QHI[bb + 4];
                    u32 bl0 = QLO[bb], bl1 = QLO[bb + 4];
                    MMA_BF16(d, ahi[kt], bh0, bh1);
                    MMA_BF16(d, ahi[kt], bl0, bl1);
                    MMA_BF16(d, alo[kt], bh0, bh1);
                }
                int rw = qb + t * 2;
                *(float2*)&ws[s0 * 132 + rw]       = make_float2(d[0], d[1]);
                *(float2*)&ws[(s0 + 8) * 132 + rw] = make_float2(d[2], d[3]);
            }
        }
        __syncthreads();

        // ---- exp phase: row r_e, slot pairs {4q+h} -> packed bf16 W planes ----
        {
            int lim = MEM - m0;
            float raw[8][2];
            float mx = -1e30f;
#pragma unroll
            for (int q = 0; q < 8; q++) {
                int s0 = q * 8 + 2 * h;
                float v0 = ws[s0 * 132 + r_e];
                float v1 = ws[(s0 + 1) * 132 + r_e];
                raw[q][0] = v0; raw[q][1] = v1;
                if (s0 < lim && v0 > mx) mx = v0;
                if (s0 + 1 < lim && v1 > mx) mx = v1;
            }
            mx = fmaxf(mx, __shfl_xor_sync(0xffffffffu, mx, 1));
            mx = fmaxf(mx, __shfl_xor_sync(0xffffffffu, mx, 2));
            float mnew = fmaxf(m, mx);
            float scl = __expf(m - mnew);
            float ls = 0.f;
#pragma unroll
            for (int q = 0; q < 8; q++) {
                int s0 = q * 8 + 2 * h;
                float w0 = (s0     < lim) ? __expf(raw[q][0] - mnew) : 0.f;
                float w1 = (s0 + 1 < lim) ? __expf(raw[q][1] - mnew) : 0.f;
                ls += w0 + w1;
                u32 hi, lo; split2(w0, w1, hi, lo);
                WPH[r_e * 36 + q * 4 + h] = hi;
                WPL[r_e * 36 + q * 4 + h] = lo;
            }
            ls += __shfl_xor_sync(0xffffffffu, ls, 1);
            ls += __shfl_xor_sync(0xffffffffu, ls, 2);
            l = l * scl + ls;
            m = mnew;
            if (h == 0) sc[r_e] = scl;
        }
        __syncthreads();

        // ---- GEMM2: rows mt2*16+g(+8), n-tiles nb2..nb2+7 ----
        {
            int r0 = mt2 * 16 + g, r1 = r0 + 8;
            float s0f = sc[r0], s1f = sc[r1];
#pragma unroll
            for (int nt = 0; nt < 8; nt++) {
                acc[nt][0] *= s0f; acc[nt][1] *= s0f;
                acc[nt][2] *= s1f; acc[nt][3] *= s1f;
            }
            u32 ahi[4][4], alo[4][4];
#pragma unroll
            for (int kt = 0; kt < 4; kt++) {
                int p0 = kt * 8 + t;
                ahi[kt][0] = WPH[r0 * 36 + p0];     ahi[kt][1] = WPH[r1 * 36 + p0];
                ahi[kt][2] = WPH[r0 * 36 + p0 + 4]; ahi[kt][3] = WPH[r1 * 36 + p0 + 4];
                alo[kt][0] = WPL[r0 * 36 + p0];     alo[kt][1] = WPL[r1 * 36 + p0];
                alo[kt][2] = WPL[r0 * 36 + p0 + 4]; alo[kt][3] = WPL[r1 * 36 + p0 + 4];
            }
#pragma unroll
            for (int nt = 0; nt < 8; nt++) {
                int cb = ((nb2 + nt) * 8 + g) * 36;
#pragma unroll
                for (int kt = 0; kt < 4; kt++) {
                    int bb = cb + 8 * kt + t;
                    u32 bh0 = VHIb[bb], bh1 = VHIb[bb + 4];
                    u32 bl0 = VLOb[bb], bl1 = VLOb[bb + 4];
                    MMA_BF16(acc[nt], ahi[kt], bh0, bh1);
                    MMA_BF16(acc[nt], ahi[kt], bl0, bl1);
                    MMA_BF16(acc[nt], alo[kt], bh0, bh1);
                }
            }
        }
    }

    if (h == 0) li[r_e] = 1.0f / l;
    __syncthreads();

    // epilogue: normalize + scalar stores (out only 4B-aligned)
    {
        int r0 = mt2 * 16 + g, r1 = r0 + 8;
        float li0 = li[r0], li1 = li[r1];
        float* op0 = outR + (size_t)(row0 + r0) * VAL;
        float* op1 = outR + (size_t)(row0 + r1) * VAL;
#pragma unroll
        for (int nt = 0; nt < 8; nt++) {
            int c = (nb2 + nt) * 8 + t * 2;
            op0[c]     = acc[nt][0] * li0;
            op0[c + 1] = acc[nt][1] * li0;
            op1[c]     = acc[nt][2] * li1;
            op1[c + 1] = acc[nt][3] * li1;
        }
    }
}

// ---------------- fused controller MLP: W1 streamed in 4 chunks -> 2 CTAs/SM ----------------
#define MLP_W1C 0                       /* [48][128] = 6144 floats; h2 aliases */
#define MLP_AUG 6144                    /* [64][193] */
#define MLP_H1  (6144 + 64 * 193)       /* [64][129] */
#define MLP_RED (MLP_H1 + 64 * 129)     /* [64] */
#define MLP_SMEM_FLOATS (MLP_RED + 64)
__global__ void __launch_bounds__(256) k_mlp(
        const float* __restrict__ qy, const float* retrIn, float* predOut,
        const float* __restrict__ W1, const float* __restrict__ b1,
        const float* __restrict__ W2, const float* __restrict__ b2,
        const float* __restrict__ W3, const float* __restrict__ b3) {
    extern __shared__ float sm[];
    float* W1c   = sm + MLP_W1C;
    float* aug_s = sm + MLP_AUG;
    float* h1_s  = sm + MLP_H1;
    float* red   = sm + MLP_RED;
    float* h2_s  = sm + MLP_W1C;        // alias: W1c dead after h1
    float* W2_s  = aug_s;               // alias: aug dead after h1
    int tid = threadIdx.x;
    int row0 = blockIdx.x * 64;

    for (int i = tid; i < 64 * 192; i += 256) {
        int r = i / 192, c = i % 192;
        float v = (c < KEY) ? g_query_feat[(row0 + r) * KEY + c]
                            : retrIn[(size_t)(row0 + r) * VAL + (c - KEY)];
        aug_s[r * 193 + c] = v;
    }

    {   // h1 = relu(aug @ W1 + b1); W1 streamed in 4 k-chunks of 48
        int r = tid & 63, g = tid >> 6;
        u64 acc[16];
#pragma unroll
        for (int c = 0; c < 16; c++) {
            float x = b1[g * 32 + 2 * c], y = b1[g * 32 + 2 * c + 1];
            PACKF_F32X2(acc[c], x, y);
        }
        for (int kc = 0; kc < 4; kc++) {
            __syncthreads();
            for (int i = tid; i < 48 * 128 / 4; i += 256)
                ((float4*)W1c)[i] = ((const float4*)(W1 + kc * 48 * 128))[i];
            __syncthreads();
            for (int k = 0; k < 48; k++) {
                float a = aug_s[r * 193 + kc * 48 + k];
                u64 a2; PACKF_F32X2(a2, a, a);
                const ulonglong2* wr = (const ulonglong2*)(W1c + k * 128 + g * 32);
#pragma unroll
                for (int q = 0; q < 8; q++) {
                    ulonglong2 wv = wr[q];
                    FMA_F32X2(acc[2 * q],     a2, wv.x, acc[2 * q]);
                    FMA_F32X2(acc[2 * q + 1], a2, wv.y, acc[2 * q + 1]);
                }
            }
        }
#pragma unroll
        for (int c = 0; c < 16; c++) {
            float x, y;
            UNPACKF_F32X2(x, y, acc[c]);
            h1_s[r * 129 + g * 32 + 2 * c]     = fmaxf(x, 0.f);
            h1_s[r * 129 + g * 32 + 2 * c + 1] = fmaxf(y, 0.f);
        }
    }
    __syncthreads();
    for (int i = tid; i < 128 * 64 / 4; i += 256)
        ((float4*)W2_s)[i] = ((const float4*)W2)[i];
    __syncthreads();

    {   // h2 = relu(h1 @ W2 + b2)
        int r = tid & 63, g = tid >> 6;
        u64 acc[8];
#pragma unroll
        for (int c = 0; c < 8; c++) {
            float x = b2[g * 16 + 2 * c], y = b2[g * 16 + 2 * c + 1];
            PACKF_F32X2(acc[c], x, y);
        }
        for (int k = 0; k < 128; k++) {
            float a = h1_s[r * 129 + k];
            u64 a2; PACKF_F32X2(a2, a, a);
            const ulonglong2* wr = (const ulonglong2*)(W2_s + k * 64 + g * 16);
#pragma unroll
            for (int q = 0; q < 4; q++) {
                ulonglong2 wv = wr[q];
                FMA_F32X2(acc[2 * q],     a2, wv.x, acc[2 * q]);
                FMA_F32X2(acc[2 * q + 1], a2, wv.y, acc[2 * q + 1]);
            }
        }
#pragma unroll
        for (int c = 0; c < 8; c++) {
            float x, y;
            UNPACKF_F32X2(x, y, acc[c]);
            h2_s[r * 65 + g * 16 + 2 * c]     = fmaxf(x, 0.f);
            h2_s[r * 65 + g * 16 + 2 * c + 1] = fmaxf(y, 0.f);
        }
    }
    __syncthreads();
    {   // pred = h2 @ W3 + b3 ; squared error partial
        int r = tid >> 2, g = tid & 3;
        float s = 0.f;
#pragma unroll
        for (int i = 0; i < 16; i++) s += h2_s[r * 65 + g * 16 + i] * W3[g * 16 + i];
        s += __shfl_xor_sync(0xffffffffu, s, 1);
        s += __shfl_xor_sync(0xffffffffu, s, 2);
        if (g == 0) {
            float p = s + b3[0];
            predOut[row0 + r] = p;
            float d = p - qy[row0 + r];
            red[r] = d * d;
        }
    }
    __syncthreads();
    if (tid < 32) {
        float v = red[tid] + red[tid + 32];
        v += __shfl_xor_sync(0xffffffffu, v, 16);
        v += __shfl_xor_sync(0xffffffffu, v, 8);
        v += __shfl_xor_sync(0xffffffffu, v, 4);
        v += __shfl_xor_sync(0xffffffffu, v, 2);
        v += __shfl_xor_sync(0xffffffffu, v, 1);
        if (tid == 0) g_loss_part[blockIdx.x] = v;
    }
}

// ---------------- deterministic loss finalize ----------------
__global__ void k_finalize(float* __restrict__ out) {
    __shared__ float s[1024];
    int t = threadIdx.x;
    s[t] = g_loss_part[t];
    __syncthreads();
    for (int st = 512; st > 0; st >>= 1) {
        if (t < st) s[t] += s[t + st];
        __syncthreads();
    }
    if (t == 0) out[0] = s[0] / (float)BQ;
}

// ---------------- launcher ----------------
extern "C" void kernel_launch(void* const* d_in, const int* in_sizes, int n_in,
                              void* d_out, int out_size) {
    const float* support_x  = (const float*)d_in[0];
    const float* support_y  = (const float*)d_in[1];
    const float* query_x    = (const float*)d_in[2];
    const float* query_y    = (const float*)d_in[3];
    const float* base_W     = (const float*)d_in[4];
    const float* base_b     = (const float*)d_in[5];
    const float* kp_W       = (const float*)d_in[6];
    const float* kp_b       = (const float*)d_in[7];
    const float* vp_W       = (const float*)d_in[8];
    const float* vp_b       = (const float*)d_in[9];
    const float* mem_keys   = (const float*)d_in[10];
    const float* mem_values = (const float*)d_in[11];
    const float* mem_age    = (const float*)d_in[12];
    const float* c1_W       = (const float*)d_in[13];
    const float* c1_b       = (const float*)d_in[14];
    const float* c2_W       = (const float*)d_in[15];
    const float* c2_b       = (const float*)d_in[16];
    const float* c3_W       = (const float*)d_in[17];
    const float* c3_b       = (const float*)d_in[18];
    float* out = (float*)d_out;

    float *p_pred_fb, *p_retr_fb;
    cudaGetSymbolAddress((void**)&p_pred_fb, g_pred_fb);
    cudaGetSymbolAddress((void**)&p_retr_fb, g_retr_fb);

    float* predBuf = (out_size >= 1 + BQ)            ? out + 1      : p_pred_fb;
    float* retrBuf = (out_size >= 1 + BQ + BQ * VAL) ? out + 1 + BQ : p_retr_fb;

    const int qf_smem  = QF_SMEM_FLOATS * 4;
    const int at_smem  = AT_SMEM_FLOATS * 4;
    const int mlp_smem = MLP_SMEM_FLOATS * 4;
    cudaFuncSetAttribute(k_qfeat, cudaFuncAttributeMaxDynamicSharedMemorySize, qf_smem);
    cudaFuncSetAttribute(k_attn,  cudaFuncAttributeMaxDynamicSharedMemorySize, at_smem);
    cudaFuncSetAttribute(k_mlp,   cudaFuncAttributeMaxDynamicSharedMemorySize, mlp_smem);

    // launch order: k_attn is the 4th launch (ncu -s window -> fresh attn profile)
    k_prep<<<388, 256>>>(support_x, support_y, base_W, base_b, kp_W, kp_b,
                         vp_W, vp_b, mem_age);
    k_scatter<<<NSLOT, 192>>>(mem_keys, mem_values);
    k_qfeat<<<BQ / 128, 256, qf_smem>>>(query_x, base_W, base_b, kp_W, kp_b);
    k_attn<<<BQ / 128, 512, at_smem>>>(retrBuf);
    k_mlp<<<BQ / 64, 256, mlp_smem>>>(query_y, retrBuf, predBuf,
                                      c1_W, c1_b, c2_W, c2_b, c3_W, c3_b);
    k_finalize<<<1, 1024>>>(out);
}